// round 8
// baseline (speedup 1.0000x reference)
#include <cuda_runtime.h>

// GINConv fused: out = A @ (X @ W)  (reassociated from (A@X) @ W)
// N=100000 nodes, E=2.5M edges (CSR), D_IN = D_OUT = 32.
// R8: edge-balanced aggregate with PRECOMPUTED per-edge row ids (fused into
// the transform kernel) — no binary search, smem-staged index broadcast.

#define MAX_N 100000
#define MAX_E 2600000
#define D 32

// Scratch (static to obey no-alloc rule):
__device__ __align__(16) float g_Y[MAX_N * D];   // Y = X @ W (12.8 MB, L2-resident)
__device__ int g_rowid[MAX_E];                   // destination row per edge (10 MB)

// packed f32x2 accumulate: a += b (two fp32 adds in one instruction)
__device__ __forceinline__ void add2(unsigned long long& a, unsigned long long b) {
    asm("add.rn.f32x2 %0, %0, %1;" : "+l"(a) : "l"(b));
}

// ---------------------------------------------------------------------------
// Kernel 1: Y = X @ W, zero-init `out`, and expand CSR rows -> g_rowid.
// One warp per 4 rows; lane (g,s): group g owns row base+g, s = quarter.
// ---------------------------------------------------------------------------
__global__ void __launch_bounds__(256) gin_transform(
    const float* __restrict__ X, const float* __restrict__ W,
    const int* __restrict__ rp, float* __restrict__ out, int n)
{
    __shared__ __align__(16) float Ws[D * D];        // 4 KB
    __shared__ __align__(16) float Xs[8][4 * 36];    // 4 rows/warp, pad stride 36

    int tid = threadIdx.x;
    for (int i = tid; i < D * D; i += blockDim.x) Ws[i] = W[i];
    __syncthreads();

    int lane = tid & 31;
    int wip  = tid >> 5;
    int warp = blockIdx.x * 8 + wip;
    int row4 = warp * 4;
    if (row4 >= n) return;

    int g = lane >> 3, s = lane & 7;
    int r = row4 + g;
    bool rv = (r < n);

    float4 xv = make_float4(0.f, 0.f, 0.f, 0.f);
    if (rv) xv = ((const float4*)X)[r * 8 + s];          // coalesced 512B/warp
    float* xrow = &Xs[wip][g * 36];
    *((float4*)(xrow + s * 4)) = xv;
    __syncwarp();

    float4 acc = make_float4(0.f, 0.f, 0.f, 0.f);
    #pragma unroll
    for (int k = 0; k < D; k++) {
        float  xk = xrow[k];
        float4 wr = ((const float4*)Ws)[k * 8 + s];      // LDS.128 broadcast
        acc.x = fmaf(xk, wr.x, acc.x);
        acc.y = fmaf(xk, wr.y, acc.y);
        acc.z = fmaf(xk, wr.z, acc.z);
        acc.w = fmaf(xk, wr.w, acc.w);
    }
    if (rv) {
        ((float4*)g_Y)[r * 8 + s] = acc;                 // coalesced 512B/warp
        ((float4*)out)[r * 8 + s] = make_float4(0.f, 0.f, 0.f, 0.f);
        // CSR expansion: group g writes its row's edge range, 8 lanes strided.
        int st = __ldg(&rp[r]);
        int en = __ldg(&rp[r + 1]);
        for (int e = st + s; e < en; e += 8) g_rowid[e] = r;
    }
}

// ---------------------------------------------------------------------------
// Kernel 2: edge-balanced aggregate. Warp w owns edges [32w, 32w+32).
// Lane l loads (col, row) for edge 32w+l (both coalesced), stages the pair in
// smem. Group g (8 lanes) then walks edges 32w+8g..+7: broadcast LDS.64 of the
// pair, one LDG.128 gathers the full 128B Y row (4 edges per warp-instr).
// Same-row runs accumulate in registers; each run flushed with red.add.v4.f32.
// ---------------------------------------------------------------------------
__global__ void __launch_bounds__(256) gin_aggregate(
    const int* __restrict__ ci, float* __restrict__ out, int nedges)
{
    __shared__ __align__(8) int2 pairs[8][32];

    int tid  = threadIdx.x;
    int lane = tid & 31;
    int wip  = tid >> 5;
    int grp  = lane >> 3, sub = lane & 7;
    int warp = blockIdx.x * 8 + wip;

    int e  = warp * 32 + lane;
    int2 p;
    if (e < nedges) {
        p.x = __ldg(&ci[e]);          // column (source row in Y)
        p.y = __ldg(&g_rowid[e]);     // destination row
    } else {
        p.x = -1; p.y = -1;
    }
    pairs[wip][lane] = p;
    __syncwarp();

    const ulonglong2* __restrict__ Y2 = (const ulonglong2*)g_Y;  // row = 8x16B

    unsigned long long a01 = 0ull, a23 = 0ull;
    int cur = -1;

    #pragma unroll
    for (int k = 0; k < 8; k++) {
        int2 q = pairs[wip][grp * 8 + k];        // broadcast LDS.64 per group
        if (q.x < 0) continue;                   // tail sentinel
        if (q.y != cur) {
            if (cur >= 0) {                      // flush previous run
                float* fp = out + (size_t)cur * D + sub * 4;
                asm volatile("red.global.add.v4.f32 [%0], {%1, %2, %3, %4};"
                    :: "l"(fp),
                       "f"(__uint_as_float((unsigned)a01)),
                       "f"(__uint_as_float((unsigned)(a01 >> 32))),
                       "f"(__uint_as_float((unsigned)a23)),
                       "f"(__uint_as_float((unsigned)(a23 >> 32)))
                    : "memory");
            }
            cur = q.y; a01 = 0ull; a23 = 0ull;
        }
        ulonglong2 v = __ldg(&Y2[(size_t)q.x * 8 + sub]); // LDG.128: 4 edges/warp
        add2(a01, v.x);
        add2(a23, v.y);
    }
    if (cur >= 0) {
        float* fp = out + (size_t)cur * D + sub * 4;
        asm volatile("red.global.add.v4.f32 [%0], {%1, %2, %3, %4};"
            :: "l"(fp),
               "f"(__uint_as_float((unsigned)a01)),
               "f"(__uint_as_float((unsigned)(a01 >> 32))),
               "f"(__uint_as_float((unsigned)a23)),
               "f"(__uint_as_float((unsigned)(a23 >> 32)))
            : "memory");
    }
}

// ---------------------------------------------------------------------------
extern "C" void kernel_launch(void* const* d_in, const int* in_sizes, int n_in,
                              void* d_out, int out_size)
{
    const float* X  = (const float*)d_in[0];
    const float* W  = (const float*)d_in[1];
    const int*   rp = (const int*)d_in[2];
    const int*   ci = (const int*)d_in[3];
    float*       out = (float*)d_out;

    int n      = in_sizes[0] / D;   // number of nodes
    int nedges = in_sizes[3];       // E

    const int THREADS = 256;
    int tblocks = (n + 31) / 32;                 // 4 rows/warp, 8 warps/block
    int chunks  = (nedges + 31) / 32;            // 32 edges per warp
    int ablocks = (chunks + 7) / 8;              // 8 warps/block

    gin_transform<<<tblocks, THREADS>>>(X, W, rp, out, n);
    gin_aggregate<<<ablocks, THREADS>>>(ci, out, nedges);
}

// round 10
// speedup vs baseline: 1.2431x; 1.2431x over previous
#include <cuda_runtime.h>

// GINConv fused: out = A @ (X @ W)  (reassociated from (A@X) @ W)
// N=100000 nodes, E=2.5M edges (CSR), D_IN = D_OUT = 32.
// R9: 3 kernels — transform (Y=X@W, zero out), warp-per-row CSR expansion
// (coalesced rowid writes), edge-balanced aggregate with MLP-8 batched gathers.

#define MAX_N 100000
#define MAX_E 2600000
#define D 32

// Scratch (static to obey no-alloc rule):
__device__ __align__(16) float g_Y[MAX_N * D];   // Y = X @ W (12.8 MB, L2-resident)
__device__ int g_rowid[MAX_E];                   // destination row per edge (10 MB)

// packed f32x2 accumulate: a += b (two fp32 adds in one instruction)
__device__ __forceinline__ void add2(unsigned long long& a, unsigned long long b) {
    asm("add.rn.f32x2 %0, %0, %1;" : "+l"(a) : "l"(b));
}

__device__ __forceinline__ void flush_v4(float* p, unsigned long long a01,
                                         unsigned long long a23) {
    asm volatile("red.global.add.v4.f32 [%0], {%1, %2, %3, %4};"
        :: "l"(p),
           "f"(__uint_as_float((unsigned)a01)),
           "f"(__uint_as_float((unsigned)(a01 >> 32))),
           "f"(__uint_as_float((unsigned)a23)),
           "f"(__uint_as_float((unsigned)(a23 >> 32)))
        : "memory");
}

// ---------------------------------------------------------------------------
// Kernel 1: Y = X @ W, zero-init `out`.
// One warp per 4 rows; lane (g,s): group g owns row base+g, s = quarter.
// ---------------------------------------------------------------------------
__global__ void __launch_bounds__(256) gin_transform(
    const float* __restrict__ X, const float* __restrict__ W,
    float* __restrict__ out, int n)
{
    __shared__ __align__(16) float Ws[D * D];        // 4 KB
    __shared__ __align__(16) float Xs[8][4 * 36];    // 4 rows/warp, pad stride 36

    int tid = threadIdx.x;
    for (int i = tid; i < D * D; i += blockDim.x) Ws[i] = W[i];
    __syncthreads();

    int lane = tid & 31;
    int wip  = tid >> 5;
    int warp = blockIdx.x * 8 + wip;
    int row4 = warp * 4;
    if (row4 >= n) return;

    int g = lane >> 3, s = lane & 7;
    int r = row4 + g;
    bool rv = (r < n);

    float4 xv = make_float4(0.f, 0.f, 0.f, 0.f);
    if (rv) xv = ((const float4*)X)[r * 8 + s];          // coalesced 512B/warp
    float* xrow = &Xs[wip][g * 36];
    *((float4*)(xrow + s * 4)) = xv;
    __syncwarp();

    float4 acc = make_float4(0.f, 0.f, 0.f, 0.f);
    #pragma unroll
    for (int k = 0; k < D; k++) {
        float  xk = xrow[k];
        float4 wr = ((const float4*)Ws)[k * 8 + s];      // LDS.128 broadcast
        acc.x = fmaf(xk, wr.x, acc.x);
        acc.y = fmaf(xk, wr.y, acc.y);
        acc.z = fmaf(xk, wr.z, acc.z);
        acc.w = fmaf(xk, wr.w, acc.w);
    }
    if (rv) {
        ((float4*)g_Y)[r * 8 + s] = acc;                 // coalesced 512B/warp
        ((float4*)out)[r * 8 + s] = make_float4(0.f, 0.f, 0.f, 0.f);
    }
}

// ---------------------------------------------------------------------------
// Kernel 1b: CSR expansion. One FULL warp per row -> coalesced 128B stores.
// ---------------------------------------------------------------------------
__global__ void __launch_bounds__(256) gin_expand(
    const int* __restrict__ rp, int n)
{
    int lane = threadIdx.x & 31;
    int warp = blockIdx.x * 8 + (threadIdx.x >> 5);
    if (warp >= n) return;
    int st = __ldg(&rp[warp]);
    int en = __ldg(&rp[warp + 1]);
    for (int e = st + lane; e < en; e += 32) g_rowid[e] = warp;
}

// ---------------------------------------------------------------------------
// Kernel 2: edge-balanced aggregate. Warp w owns edges [32w, 32w+32).
// Lane l loads (col, row) coalesced and stages the pair in smem. Group g
// (8 lanes) then: PHASE A issues all 8 gather LDG.128s into registers
// (MLP=8), PHASE B does the segmented accumulate, flushing each same-row run
// with one red.global.add.v4.f32 per lane.
// ---------------------------------------------------------------------------
__global__ void __launch_bounds__(256) gin_aggregate(
    const int* __restrict__ ci, float* __restrict__ out, int nedges)
{
    __shared__ __align__(8) int2 pairs[8][32];

    int tid  = threadIdx.x;
    int lane = tid & 31;
    int wip  = tid >> 5;
    int grp  = lane >> 3, sub = lane & 7;
    int warp = blockIdx.x * 8 + wip;

    int e = warp * 32 + lane;
    int2 p;
    if (e < nedges) {
        p.x = __ldg(&ci[e]);          // column (source row in Y)
        p.y = __ldg(&g_rowid[e]);     // destination row
    } else {
        p.x = 0; p.y = -1;            // safe gather addr, invalid row
    }
    pairs[wip][lane] = p;
    __syncwarp();

    const ulonglong2* __restrict__ Y2 = (const ulonglong2*)g_Y;  // row = 8x16B

    // PHASE A: batch all 8 independent gathers (1 LDG.128 = 4 edges/warp)
    ulonglong2 v[8];
    int rows[8];
    #pragma unroll
    for (int k = 0; k < 8; k++) {
        int2 q = pairs[wip][grp * 8 + k];                // broadcast LDS.64
        rows[k] = q.y;
        v[k] = __ldg(&Y2[(size_t)q.x * 8 + sub]);
    }

    // PHASE B: segmented accumulate over the 8 edges of this group
    unsigned long long a01 = 0ull, a23 = 0ull;
    int cur = -1;
    #pragma unroll
    for (int k = 0; k < 8; k++) {
        int r = rows[k];
        if (r < 0) continue;                             // tail sentinel
        if (r != cur) {
            if (cur >= 0)
                flush_v4(out + (size_t)cur * D + sub * 4, a01, a23);
            cur = r; a01 = 0ull; a23 = 0ull;
        }
        add2(a01, v[k].x);
        add2(a23, v[k].y);
    }
    if (cur >= 0)
        flush_v4(out + (size_t)cur * D + sub * 4, a01, a23);
}

// ---------------------------------------------------------------------------
extern "C" void kernel_launch(void* const* d_in, const int* in_sizes, int n_in,
                              void* d_out, int out_size)
{
    const float* X  = (const float*)d_in[0];
    const float* W  = (const float*)d_in[1];
    const int*   rp = (const int*)d_in[2];
    const int*   ci = (const int*)d_in[3];
    float*       out = (float*)d_out;

    int n      = in_sizes[0] / D;   // number of nodes
    int nedges = in_sizes[3];       // E

    const int THREADS = 256;
    int tblocks = (n + 31) / 32;                 // 4 rows/warp, 8 warps/block
    int xblocks = (n + 7) / 8;                   // 1 row/warp,  8 warps/block
    int chunks  = (nedges + 31) / 32;            // 32 edges per warp
    int ablocks = (chunks + 7) / 8;              // 8 warps/block

    gin_transform<<<tblocks, THREADS>>>(X, W, out, n);
    gin_expand<<<xblocks, THREADS>>>(rp, n);
    gin_aggregate<<<ablocks, THREADS>>>(ci, out, nedges);
}

// round 15
// speedup vs baseline: 1.2871x; 1.0354x over previous
#include <cuda_runtime.h>

// GINConv fused: out = A @ (X @ W)  (reassociated from (A@X) @ W)
// N=100000 nodes, E=2.5M edges (CSR), D_IN = D_OUT = 32.
// R12: R11 with the shfl-binary-search depth fixed (6 steps for 33 outcomes)
// and tail-warp g_warpstart clamp.

#define MAX_N 100000
#define MAX_E 2600000
#define D 32
#define MAX_CHUNKS ((MAX_E + 31) / 32)

// Scratch (static to obey no-alloc rule):
__device__ __align__(16) float g_Y[MAX_N * D];   // Y = X @ W (12.8 MB, L2-resident)
__device__ int g_warpstart[MAX_CHUNKS];          // row of first edge per chunk (312 KB)

// packed f32x2 accumulate: a += b (two fp32 adds in one instruction)
__device__ __forceinline__ void add2(unsigned long long& a, unsigned long long b) {
    asm("add.rn.f32x2 %0, %0, %1;" : "+l"(a) : "l"(b));
}

__device__ __forceinline__ void flush_v4(float* p, unsigned long long a01,
                                         unsigned long long a23) {
    asm volatile("red.global.add.v4.f32 [%0], {%1, %2, %3, %4};"
        :: "l"(p),
           "f"(__uint_as_float((unsigned)a01)),
           "f"(__uint_as_float((unsigned)(a01 >> 32))),
           "f"(__uint_as_float((unsigned)a23)),
           "f"(__uint_as_float((unsigned)(a23 >> 32)))
        : "memory");
}

// ---------------------------------------------------------------------------
// Kernel 1 (role-split by block):
//   blocks [0, tblocks):       Y = X @ W, zero-init `out` (4 rows/warp)
//   blocks [tblocks, gridDim): g_warpstart[c] = row(32c) via binary search
// ---------------------------------------------------------------------------
__global__ void __launch_bounds__(256) gin_prep(
    const float* __restrict__ X, const float* __restrict__ W,
    const int* __restrict__ rp, float* __restrict__ out,
    int n, int tblocks, int nchunks)
{
    __shared__ __align__(16) float Ws[D * D];
    __shared__ __align__(16) float Xs[8][4 * 36];

    int tid = threadIdx.x;

    if (blockIdx.x >= tblocks) {
        // ---- warpstart role: one thread per 32-edge chunk ----
        int c = (blockIdx.x - tblocks) * 256 + tid;
        if (c < nchunks) {
            int e0 = c * 32;
            int lo = 0, hi = n - 1;            // largest r with rp[r] <= e0
            #pragma unroll 1
            while (lo < hi) {
                int mid = (lo + hi + 1) >> 1;
                if (__ldg(&rp[mid]) <= e0) lo = mid; else hi = mid - 1;
            }
            g_warpstart[c] = lo;
        }
        return;
    }

    // ---- transform role ----
    for (int i = tid; i < D * D; i += 256) Ws[i] = W[i];
    __syncthreads();

    int lane = tid & 31;
    int wip  = tid >> 5;
    int warp = blockIdx.x * 8 + wip;
    int row4 = warp * 4;
    if (row4 >= n) return;

    int g = lane >> 3, s = lane & 7;
    int r = row4 + g;
    bool rv = (r < n);

    float4 xv = make_float4(0.f, 0.f, 0.f, 0.f);
    if (rv) xv = ((const float4*)X)[r * 8 + s];          // coalesced 512B/warp
    float* xrow = &Xs[wip][g * 36];
    *((float4*)(xrow + s * 4)) = xv;
    __syncwarp();

    float4 acc = make_float4(0.f, 0.f, 0.f, 0.f);
    #pragma unroll
    for (int k = 0; k < D; k++) {
        float  xk = xrow[k];
        float4 wr = ((const float4*)Ws)[k * 8 + s];      // LDS.128 broadcast
        acc.x = fmaf(xk, wr.x, acc.x);
        acc.y = fmaf(xk, wr.y, acc.y);
        acc.z = fmaf(xk, wr.z, acc.z);
        acc.w = fmaf(xk, wr.w, acc.w);
    }
    if (rv) {
        ((float4*)g_Y)[r * 8 + s] = acc;                 // coalesced 512B/warp
        ((float4*)out)[r * 8 + s] = make_float4(0.f, 0.f, 0.f, 0.f);
    }
}

// ---------------------------------------------------------------------------
// Kernel 2: edge-balanced aggregate. Warp w owns edges [32w, 32w+32).
// Row reconstruction: sr = g_warpstart[w]; lane loads rp[sr+1+lane] (one
// coalesced LDG); lane's row = sr + (# window values <= its edge id), found
// by a 6-step shfl binary search over positions [0,32]. Rare spans > 32
// rows fall back to a global binary search. Then: stage (col,row) in smem,
// PHASE A batches 8 gather LDG.128s (MLP=8), PHASE B segmented-accumulates
// and flushes runs with red.global.add.v4.f32.
// ---------------------------------------------------------------------------
__global__ void __launch_bounds__(256) gin_aggregate(
    const int* __restrict__ rp, const int* __restrict__ ci,
    float* __restrict__ out, int n, int nedges, int nchunks)
{
    __shared__ __align__(8) int2 pairs[8][32];

    int tid  = threadIdx.x;
    int lane = tid & 31;
    int wip  = tid >> 5;
    int grp  = lane >> 3, sub = lane & 7;
    int warp = blockIdx.x * 8 + wip;

    int e = warp * 32 + lane;
    bool valid = (e < nedges);
    int ec = valid ? e : nedges - 1;

    int myc = valid ? __ldg(&ci[e]) : 0;       // coalesced; 0 = safe gather addr

    int sr = (warp < nchunks) ? __ldg(&g_warpstart[warp]) : 0;  // uniform

    // window load: rp[sr+1+lane], sentinel +inf past the end
    int widx = sr + 1 + lane;
    int wv = (widx <= n) ? __ldg(&rp[widx]) : 0x7fffffff;

    // first position p in [0,32] with wv[p] > ec  ->  count of values <= ec
    // 33 outcomes -> 6 binary-search steps (5 was the R11 bug).
    int lo = 0, hi = 32;
    #pragma unroll
    for (int it = 0; it < 6; it++) {
        int mid = (lo + hi) >> 1;              // in [0,31] whenever lo < hi
        int v = __shfl_sync(0xffffffffu, wv, mid & 31);
        if (lo < hi) { if (v <= ec) lo = mid + 1; else hi = mid; }
    }
    int myrow = sr + lo;

    if (lo == 32) {                            // rare: chunk spans >32 rows
        int slo = sr + 32, shi = n - 1;        // rp[sr+32] <= ec known
        if (slo > shi) slo = shi;
        #pragma unroll 1
        while (slo < shi) {
            int mid = (slo + shi + 1) >> 1;
            if (__ldg(&rp[mid]) <= ec) slo = mid; else shi = mid - 1;
        }
        myrow = slo;
    }
    if (!valid) myrow = -1;

    int2 p; p.x = myc; p.y = myrow;
    pairs[wip][lane] = p;
    __syncwarp();

    const ulonglong2* __restrict__ Y2 = (const ulonglong2*)g_Y;  // row = 8x16B

    // PHASE A: batch all 8 independent gathers (1 LDG.128 = 4 edges/warp)
    ulonglong2 v[8];
    int rows[8];
    #pragma unroll
    for (int k = 0; k < 8; k++) {
        int2 q = pairs[wip][grp * 8 + k];                // broadcast LDS.64
        rows[k] = q.y;
        v[k] = __ldg(&Y2[(size_t)q.x * 8 + sub]);
    }

    // PHASE B: segmented accumulate over the 8 edges of this group
    unsigned long long a01 = 0ull, a23 = 0ull;
    int cur = -1;
    #pragma unroll
    for (int k = 0; k < 8; k++) {
        int r = rows[k];
        if (r < 0) continue;                             // tail sentinel
        if (r != cur) {
            if (cur >= 0)
                flush_v4(out + (size_t)cur * D + sub * 4, a01, a23);
            cur = r; a01 = 0ull; a23 = 0ull;
        }
        add2(a01, v[k].x);
        add2(a23, v[k].y);
    }
    if (cur >= 0)
        flush_v4(out + (size_t)cur * D + sub * 4, a01, a23);
}

// ---------------------------------------------------------------------------
extern "C" void kernel_launch(void* const* d_in, const int* in_sizes, int n_in,
                              void* d_out, int out_size)
{
    const float* X  = (const float*)d_in[0];
    const float* W  = (const float*)d_in[1];
    const int*   rp = (const int*)d_in[2];
    const int*   ci = (const int*)d_in[3];
    float*       out = (float*)d_out;

    int n      = in_sizes[0] / D;   // number of nodes
    int nedges = in_sizes[3];       // E

    const int THREADS = 256;
    int tblocks = (n + 31) / 32;                 // transform: 4 rows/warp
    int nchunks = (nedges + 31) / 32;            // 32 edges per warp
    int wblocks = (nchunks + 255) / 256;         // warpstart role
    int ablocks = (nchunks + 7) / 8;             // aggregate: 8 warps/block

    gin_prep<<<tblocks + wblocks, THREADS>>>(X, W, rp, out, n, tblocks, nchunks);
    gin_aggregate<<<ablocks, THREADS>>>(rp, ci, out, n, nedges, nchunks);
}